// round 2
// baseline (speedup 1.0000x reference)
#include <cuda_runtime.h>
#include <math.h>
#include <math_constants.h>

#define HDIM 256
#define MAXB 1024
#define MAXN 32768

// Scratch: __device__ globals (no dynamic allocation allowed).
__device__ float g_q[(size_t)MAXB * HDIM];
__device__ float g_k[(size_t)MAXN * HDIM];
__device__ float g_v[(size_t)MAXN * HDIM];

// ---------------------------------------------------------------------------
// C[M, 256] = relu(A[M,256] @ W[256,256] + bias) * scale
// 64x64 block tile, 16 k-slice, 16x16 threads, 4x4 microtile.
// Fused K/V variant: blockIdx.z selects (W0,b0,C0) vs (W1,b1,C1).
// ---------------------------------------------------------------------------
__global__ void __launch_bounds__(256) gemm_bias_relu_kv(
    const float* __restrict__ A,
    const float* __restrict__ W0, const float* __restrict__ b0f, float* __restrict__ C0,
    const float* __restrict__ W1, const float* __restrict__ b1f, float* __restrict__ C1)
{
    __shared__ float As[16][65];   // [k][m], padded against store conflicts
    __shared__ float Ws[16][64];   // [k][n]

    const float* W    = blockIdx.z ? W1  : W0;
    const float* bias = blockIdx.z ? b1f : b0f;
    float*       C    = blockIdx.z ? C1  : C0;

    const int tid = threadIdx.x;
    const int bm = blockIdx.y * 64;
    const int bn = blockIdx.x * 64;
    const int tx = tid & 15;
    const int ty = tid >> 4;

    const int lm  = tid >> 2;          // 0..63
    const int lk4 = (tid & 3) * 4;     // 0,4,8,12
    const int lwk = tid >> 4;          // 0..15
    const int lwn = (tid & 15) * 4;    // 0..60

    const float* Arow = A + (size_t)(bm + lm) * HDIM;

    float acc[4][4] = {};

    for (int k0 = 0; k0 < HDIM; k0 += 16) {
        float4 a4 = *(const float4*)(Arow + k0 + lk4);
        float4 w4 = *(const float4*)(W + (size_t)(k0 + lwk) * HDIM + bn + lwn);
        As[lk4 + 0][lm] = a4.x;
        As[lk4 + 1][lm] = a4.y;
        As[lk4 + 2][lm] = a4.z;
        As[lk4 + 3][lm] = a4.w;
        *(float4*)&Ws[lwk][lwn] = w4;
        __syncthreads();

        #pragma unroll
        for (int kk = 0; kk < 16; kk++) {
            float a[4], w[4];
            #pragma unroll
            for (int i = 0; i < 4; i++) a[i] = As[kk][ty * 4 + i];
            #pragma unroll
            for (int j = 0; j < 4; j++) w[j] = Ws[kk][tx * 4 + j];
            #pragma unroll
            for (int i = 0; i < 4; i++)
                #pragma unroll
                for (int j = 0; j < 4; j++)
                    acc[i][j] = fmaf(a[i], w[j], acc[i][j]);
        }
        __syncthreads();
    }

    const int col = bn + tx * 4;
    float c0 = bias[col + 0], c1 = bias[col + 1], c2 = bias[col + 2], c3 = bias[col + 3];
    #pragma unroll
    for (int i = 0; i < 4; i++) {
        const int row = bm + ty * 4 + i;
        float4 r;
        r.x = fmaxf(acc[i][0] + c0, 0.f);
        r.y = fmaxf(acc[i][1] + c1, 0.f);
        r.z = fmaxf(acc[i][2] + c2, 0.f);
        r.w = fmaxf(acc[i][3] + c3, 0.f);
        *(float4*)(C + (size_t)row * HDIM + col) = r;
    }
}

// Q GEMM (single weight, post-ReLU scale).
__global__ void __launch_bounds__(256) gemm_bias_relu(
    const float* __restrict__ A,
    const float* __restrict__ W,
    const float* __restrict__ bias,
    float* __restrict__ C,
    float scale)
{
    __shared__ float As[16][65];
    __shared__ float Ws[16][64];

    const int tid = threadIdx.x;
    const int bm = blockIdx.y * 64;
    const int bn = blockIdx.x * 64;
    const int tx = tid & 15;
    const int ty = tid >> 4;

    const int lm  = tid >> 2;
    const int lk4 = (tid & 3) * 4;
    const int lwk = tid >> 4;
    const int lwn = (tid & 15) * 4;

    const float* Arow = A + (size_t)(bm + lm) * HDIM;

    float acc[4][4] = {};

    for (int k0 = 0; k0 < HDIM; k0 += 16) {
        float4 a4 = *(const float4*)(Arow + k0 + lk4);
        float4 w4 = *(const float4*)(W + (size_t)(k0 + lwk) * HDIM + bn + lwn);
        As[lk4 + 0][lm] = a4.x;
        As[lk4 + 1][lm] = a4.y;
        As[lk4 + 2][lm] = a4.z;
        As[lk4 + 3][lm] = a4.w;
        *(float4*)&Ws[lwk][lwn] = w4;
        __syncthreads();

        #pragma unroll
        for (int kk = 0; kk < 16; kk++) {
            float a[4], w[4];
            #pragma unroll
            for (int i = 0; i < 4; i++) a[i] = As[kk][ty * 4 + i];
            #pragma unroll
            for (int j = 0; j < 4; j++) w[j] = Ws[kk][tx * 4 + j];
            #pragma unroll
            for (int i = 0; i < 4; i++)
                #pragma unroll
                for (int j = 0; j < 4; j++)
                    acc[i][j] = fmaf(a[i], w[j], acc[i][j]);
        }
        __syncthreads();
    }

    const int col = bn + tx * 4;
    float c0 = bias[col + 0], c1 = bias[col + 1], c2 = bias[col + 2], c3 = bias[col + 3];
    #pragma unroll
    for (int i = 0; i < 4; i++) {
        const int row = bm + ty * 4 + i;
        float4 r;
        r.x = fmaxf(acc[i][0] + c0, 0.f) * scale;
        r.y = fmaxf(acc[i][1] + c1, 0.f) * scale;
        r.z = fmaxf(acc[i][2] + c2, 0.f) * scale;
        r.w = fmaxf(acc[i][3] + c3, 0.f) * scale;
        *(float4*)(C + (size_t)row * HDIM + col) = r;
    }
}

// ---------------------------------------------------------------------------
// Per-sample windowed attention: one block (256 threads) per sample.
// ---------------------------------------------------------------------------
__global__ void __launch_bounds__(256) attn_kernel(
    const int* __restrict__ starts,
    const int* __restrict__ ends,
    float* __restrict__ out)
{
    const int i = blockIdx.x;
    const int tid = threadIdx.x;
    const int warp = tid >> 5;
    const int lane = tid & 31;

    __shared__ float qs[HDIM];
    __shared__ float sc[64];
    __shared__ float redbuf[8];

    qs[tid] = g_q[(size_t)i * HDIM + tid];
    const int s = starts[i];
    const int nn = ends[i] - s;   // guaranteed >= 1
    __syncthreads();

    // Scores: warp w handles neighbors w, w+8, ...
    for (int j = warp; j < nn; j += 8) {
        const float* krow = g_k + (size_t)(s + j) * HDIM;
        float acc = 0.f;
        #pragma unroll
        for (int c = 0; c < HDIM / 32; c++)
            acc = fmaf(qs[lane + 32 * c], krow[lane + 32 * c], acc);
        #pragma unroll
        for (int o = 16; o; o >>= 1)
            acc += __shfl_xor_sync(0xffffffffu, acc, o);
        if (lane == 0) sc[j] = acc;
    }
    __syncthreads();

    // Softmax over sc[0..nn) — threads 0..63 participate (2 warps).
    float x = -CUDART_INF_F;
    if (tid < 64) {
        x = (tid < nn) ? sc[tid] : -CUDART_INF_F;
        float m = x;
        #pragma unroll
        for (int o = 16; o; o >>= 1)
            m = fmaxf(m, __shfl_xor_sync(0xffffffffu, m, o));
        if (lane == 0) redbuf[warp] = m;
    }
    __syncthreads();
    const float m = fmaxf(redbuf[0], redbuf[1]);
    float p = 0.f;
    if (tid < 64) {
        p = (tid < nn) ? expf(x - m) : 0.f;
        float ssum = p;
        #pragma unroll
        for (int o = 16; o; o >>= 1)
            ssum += __shfl_xor_sync(0xffffffffu, ssum, o);
        if (lane == 0) redbuf[4 + warp] = ssum;
    }
    __syncthreads();
    const float inv = 1.f / (redbuf[4] + redbuf[5]);
    if (tid < 64) sc[tid] = p * inv;
    __syncthreads();

    // Output: thread tid owns column tid. v loads are fully coalesced.
    float acc = 0.f;
    for (int j = 0; j < nn; j++)
        acc = fmaf(sc[j], g_v[(size_t)(s + j) * HDIM + tid], acc);
    out[(size_t)i * HDIM + tid] = acc;
}

// ---------------------------------------------------------------------------
extern "C" void kernel_launch(void* const* d_in, const int* in_sizes, int n_in,
                              void* d_out, int out_size)
{
    const float* enc     = (const float*)d_in[0];   // [B, H]
    const float* social  = (const float*)d_in[1];   // [N, H]
    const int*   starts  = (const int*)  d_in[2];   // [B]
    const int*   ends    = (const int*)  d_in[3];   // [B]
    const float* Wq      = (const float*)d_in[4];
    const float* bq      = (const float*)d_in[5];
    const float* Wk      = (const float*)d_in[6];
    const float* bk      = (const float*)d_in[7];
    const float* Wv      = (const float*)d_in[8];
    const float* bv      = (const float*)d_in[9];
    float* out = (float*)d_out;

    const int B = in_sizes[0] / HDIM;
    const int N = in_sizes[1] / HDIM;

    float *qbuf, *kbuf, *vbuf;
    cudaGetSymbolAddress((void**)&qbuf, g_q);
    cudaGetSymbolAddress((void**)&kbuf, g_k);
    cudaGetSymbolAddress((void**)&vbuf, g_v);

    const float inv_sqrt_d = 1.0f / sqrtf((float)HDIM);

    dim3 blk(256);
    dim3 gkv(HDIM / 64, N / 64, 2);   // fused K+V GEMM: (4, 512, 2)
    dim3 gq(HDIM / 64, B / 64);       // Q GEMM:         (4, 16)

    gemm_bias_relu_kv<<<gkv, blk>>>(social, Wk, bk, kbuf, Wv, bv, vbuf);
    gemm_bias_relu<<<gq, blk>>>(enc, Wq, bq, qbuf, inv_sqrt_d);
    attn_kernel<<<B, blk>>>(starts, ends, out);
}

// round 4
// speedup vs baseline: 1.9314x; 1.9314x over previous
#include <cuda_runtime.h>
#include <cuda_bf16.h>
#include <math.h>
#include <math_constants.h>
#include <cstdint>

#define HDIM 256
#define MAXB 1024
#define MAXN 32768

// ---------------------------------------------------------------------------
// Scratch (__device__ globals; no dynamic allocation allowed)
// ---------------------------------------------------------------------------
__device__ float g_q[(size_t)MAXB * HDIM];
__device__ float g_k[(size_t)MAXN * HDIM];
__device__ float g_v[(size_t)MAXN * HDIM];
__device__ __nv_bfloat16 g_ahi[(size_t)MAXN * HDIM];   // split of social_ht
__device__ __nv_bfloat16 g_alo[(size_t)MAXN * HDIM];
__device__ __nv_bfloat16 g_wkt_hi[HDIM * HDIM];        // W^T splits: [n][k], k contiguous
__device__ __nv_bfloat16 g_wkt_lo[HDIM * HDIM];
__device__ __nv_bfloat16 g_wvt_hi[HDIM * HDIM];
__device__ __nv_bfloat16 g_wvt_lo[HDIM * HDIM];

// ---------------------------------------------------------------------------
// Prep: split fp32 -> (hi, lo) bf16 pair.  a = hi + lo to ~16 mantissa bits.
// ---------------------------------------------------------------------------
__global__ void __launch_bounds__(256) split_a_kernel(
    const float* __restrict__ src, __nv_bfloat16* __restrict__ hi, __nv_bfloat16* __restrict__ lo)
{
    const size_t base = ((size_t)blockIdx.x * 256 + threadIdx.x) * 8;
    float4 a = *(const float4*)(src + base);
    float4 b = *(const float4*)(src + base + 4);
    __nv_bfloat16 h[8], l[8];
    float v[8] = {a.x, a.y, a.z, a.w, b.x, b.y, b.z, b.w};
    #pragma unroll
    for (int i = 0; i < 8; i++) {
        h[i] = __float2bfloat16(v[i]);
        l[i] = __float2bfloat16(v[i] - __bfloat162float(h[i]));
    }
    *(uint4*)(hi + base) = *(const uint4*)h;
    *(uint4*)(lo + base) = *(const uint4*)l;
}

// Transpose + split both weight matrices: out[n][k] = split(W[k][n])
__global__ void __launch_bounds__(256) split_w_kernel(
    const float* __restrict__ Wk, const float* __restrict__ Wv,
    __nv_bfloat16* __restrict__ khi, __nv_bfloat16* __restrict__ klo,
    __nv_bfloat16* __restrict__ vhi, __nv_bfloat16* __restrict__ vlo)
{
    const int n = blockIdx.x, k = threadIdx.x;
    const float* W = blockIdx.y ? Wv : Wk;
    __nv_bfloat16* oh = blockIdx.y ? vhi : khi;
    __nv_bfloat16* ol = blockIdx.y ? vlo : klo;
    float a = W[k * HDIM + n];
    __nv_bfloat16 h = __float2bfloat16(a);
    oh[n * HDIM + k] = h;
    ol[n * HDIM + k] = __float2bfloat16(a - __bfloat162float(h));
}

// ---------------------------------------------------------------------------
// K/V GEMM via mma.sync.m16n8k16.bf16 (baseline PTX — compiles on compute_100).
// C[128,128] tile = relu(A @ W^T + bias); 3-MMA split: hi*hi + hi*lo + lo*hi.
// 8 warps = 4(m) x 2(n); warp tile 32x64 = 2 x 8 mma tiles.
// ---------------------------------------------------------------------------
#define KC 64                       // smem K-chunk (bf16 elems)
#define SROW 72                     // padded smem row stride (elems); 144 B
#define TILE_ELEMS (128 * SROW)     // per operand array
#define SMEM_ELEMS (4 * TILE_ELEMS) // Ahi, Alo, Bhi, Blo
#define SMEM_BYTES (SMEM_ELEMS * 2) // 73728

__device__ __forceinline__ uint32_t lds32(const __nv_bfloat16* p, int elem_off) {
    return *(const uint32_t*)(p + elem_off);
}
__device__ __forceinline__ void mma_bf16(float* d, const uint32_t* a, uint32_t b0, uint32_t b1) {
    asm volatile(
        "mma.sync.aligned.m16n8k16.row.col.f32.bf16.bf16.f32 "
        "{%0,%1,%2,%3}, {%4,%5,%6,%7}, {%8,%9}, {%0,%1,%2,%3};\n"
        : "+f"(d[0]), "+f"(d[1]), "+f"(d[2]), "+f"(d[3])
        : "r"(a[0]), "r"(a[1]), "r"(a[2]), "r"(a[3]), "r"(b0), "r"(b1));
}

__global__ void __launch_bounds__(256, 1) kv_mma_kernel(
    const float* __restrict__ bk, const float* __restrict__ bv)
{
    extern __shared__ __nv_bfloat16 sm[];
    __nv_bfloat16* sAhi = sm;
    __nv_bfloat16* sAlo = sm + TILE_ELEMS;
    __nv_bfloat16* sBhi = sm + 2 * TILE_ELEMS;
    __nv_bfloat16* sBlo = sm + 3 * TILE_ELEMS;

    const int tid = threadIdx.x;
    const int wid = tid >> 5;
    const int lane = tid & 31;
    const int grp = lane >> 2;      // 0..7
    const int qid = lane & 3;       // 0..3
    const int warp_m = wid & 3;     // 4 warps along m (32 rows each)
    const int warp_n = wid >> 2;    // 2 warps along n (64 cols each)

    const int bn = blockIdx.x;      // n-tile (0..1)
    const int bm = blockIdx.y;      // m-tile (0..255)
    const int mat = blockIdx.z;     // 0 = K, 1 = V

    const __nv_bfloat16* gBhi = mat ? g_wvt_hi : g_wkt_hi;
    const __nv_bfloat16* gBlo = mat ? g_wvt_lo : g_wkt_lo;
    float* C = mat ? g_v : g_k;
    const float* bias = mat ? bv : bk;

    // Global load geometry: 128 rows x 64 cols per array; thread loads 4
    // segments of 8 bf16 (16B).  seg = tid + u*256; row = seg>>3, colseg = seg&7.
    const __nv_bfloat16* gsrc[4] = {g_ahi, g_alo, gBhi, gBlo};
    __nv_bfloat16* sdst[4] = {sAhi, sAlo, sBhi, sBlo};
    const int grow[4] = {bm * 128, bm * 128, bn * 128, bn * 128};

    float acc[2][8][4] = {};

    for (int c0 = 0; c0 < HDIM; c0 += KC) {
        #pragma unroll
        for (int arr = 0; arr < 4; arr++) {
            const __nv_bfloat16* src = gsrc[arr] + (size_t)grow[arr] * HDIM + c0;
            __nv_bfloat16* dst = sdst[arr];
            #pragma unroll
            for (int u = 0; u < 4; u++) {
                int seg = u * 256 + tid;
                int row = seg >> 3, cs = seg & 7;
                uint4 v = *(const uint4*)(src + (size_t)row * HDIM + cs * 8);
                *(uint4*)(dst + row * SROW + cs * 8) = v;
            }
        }
        __syncthreads();

        #pragma unroll
        for (int ks = 0; ks < KC / 16; ks++) {
            const int k0 = ks * 16;
            // A fragments for the 2 m16 blocks (hi and lo)
            uint32_t ahi[2][4], alo[2][4];
            #pragma unroll
            for (int mi = 0; mi < 2; mi++) {
                const int abase = (warp_m * 32 + mi * 16 + grp) * SROW + k0 + 2 * qid;
                ahi[mi][0] = lds32(sAhi, abase);
                ahi[mi][1] = lds32(sAhi, abase + 8 * SROW);
                ahi[mi][2] = lds32(sAhi, abase + 8);
                ahi[mi][3] = lds32(sAhi, abase + 8 * SROW + 8);
                alo[mi][0] = lds32(sAlo, abase);
                alo[mi][1] = lds32(sAlo, abase + 8 * SROW);
                alo[mi][2] = lds32(sAlo, abase + 8);
                alo[mi][3] = lds32(sAlo, abase + 8 * SROW + 8);
            }
            #pragma unroll
            for (int nb = 0; nb < 8; nb++) {
                const int bbase = (warp_n * 64 + nb * 8 + grp) * SROW + k0 + 2 * qid;
                uint32_t bh0 = lds32(sBhi, bbase), bh1 = lds32(sBhi, bbase + 8);
                uint32_t bl0 = lds32(sBlo, bbase), bl1 = lds32(sBlo, bbase + 8);
                #pragma unroll
                for (int mi = 0; mi < 2; mi++) {
                    mma_bf16(acc[mi][nb], ahi[mi], bh0, bh1);
                    mma_bf16(acc[mi][nb], ahi[mi], bl0, bl1);
                    mma_bf16(acc[mi][nb], alo[mi], bh0, bh1);
                }
            }
        }
        __syncthreads();
    }

    // Epilogue: bias + relu, fp32 stores.
    #pragma unroll
    for (int mi = 0; mi < 2; mi++) {
        const int row = bm * 128 + warp_m * 32 + mi * 16 + grp;
        #pragma unroll
        for (int nb = 0; nb < 8; nb++) {
            const int col = bn * 128 + warp_n * 64 + nb * 8 + 2 * qid;
            float2 bz = *(const float2*)(bias + col);
            float2 o0, o1;
            o0.x = fmaxf(acc[mi][nb][0] + bz.x, 0.f);
            o0.y = fmaxf(acc[mi][nb][1] + bz.y, 0.f);
            o1.x = fmaxf(acc[mi][nb][2] + bz.x, 0.f);
            o1.y = fmaxf(acc[mi][nb][3] + bz.y, 0.f);
            *(float2*)(C + (size_t)row * HDIM + col) = o0;
            *(float2*)(C + (size_t)(row + 8) * HDIM + col) = o1;
        }
    }
}

// ---------------------------------------------------------------------------
// Q GEMM (scalar, tiny: 1024x256x256) — unchanged, known-correct.
// ---------------------------------------------------------------------------
__global__ void __launch_bounds__(256) gemm_bias_relu(
    const float* __restrict__ A, const float* __restrict__ W,
    const float* __restrict__ bias, float* __restrict__ C, float scale)
{
    __shared__ float As[16][65];
    __shared__ float Ws[16][64];
    const int tid = threadIdx.x;
    const int bm = blockIdx.y * 64, bn = blockIdx.x * 64;
    const int tx = tid & 15, ty = tid >> 4;
    const int lm = tid >> 2, lk4 = (tid & 3) * 4;
    const int lwk = tid >> 4, lwn = (tid & 15) * 4;
    const float* Arow = A + (size_t)(bm + lm) * HDIM;
    float acc[4][4] = {};
    for (int k0 = 0; k0 < HDIM; k0 += 16) {
        float4 a4 = *(const float4*)(Arow + k0 + lk4);
        float4 w4 = *(const float4*)(W + (size_t)(k0 + lwk) * HDIM + bn + lwn);
        As[lk4 + 0][lm] = a4.x; As[lk4 + 1][lm] = a4.y;
        As[lk4 + 2][lm] = a4.z; As[lk4 + 3][lm] = a4.w;
        *(float4*)&Ws[lwk][lwn] = w4;
        __syncthreads();
        #pragma unroll
        for (int kk = 0; kk < 16; kk++) {
            float a[4], w[4];
            #pragma unroll
            for (int i = 0; i < 4; i++) a[i] = As[kk][ty * 4 + i];
            #pragma unroll
            for (int j = 0; j < 4; j++) w[j] = Ws[kk][tx * 4 + j];
            #pragma unroll
            for (int i = 0; i < 4; i++)
                #pragma unroll
                for (int j = 0; j < 4; j++)
                    acc[i][j] = fmaf(a[i], w[j], acc[i][j]);
        }
        __syncthreads();
    }
    const int col = bn + tx * 4;
    float c0 = bias[col], c1 = bias[col + 1], c2 = bias[col + 2], c3 = bias[col + 3];
    #pragma unroll
    for (int i = 0; i < 4; i++) {
        const int row = bm + ty * 4 + i;
        float4 r;
        r.x = fmaxf(acc[i][0] + c0, 0.f) * scale;
        r.y = fmaxf(acc[i][1] + c1, 0.f) * scale;
        r.z = fmaxf(acc[i][2] + c2, 0.f) * scale;
        r.w = fmaxf(acc[i][3] + c3, 0.f) * scale;
        *(float4*)(C + (size_t)row * HDIM + col) = r;
    }
}

// ---------------------------------------------------------------------------
// Windowed attention — unchanged, known-correct.
// ---------------------------------------------------------------------------
__global__ void __launch_bounds__(256) attn_kernel(
    const int* __restrict__ starts, const int* __restrict__ ends, float* __restrict__ out)
{
    const int i = blockIdx.x;
    const int tid = threadIdx.x;
    const int warp = tid >> 5, lane = tid & 31;
    __shared__ float qs[HDIM];
    __shared__ float sc[64];
    __shared__ float redbuf[8];
    qs[tid] = g_q[(size_t)i * HDIM + tid];
    const int s = starts[i];
    const int nn = ends[i] - s;
    __syncthreads();
    for (int j = warp; j < nn; j += 8) {
        const float* krow = g_k + (size_t)(s + j) * HDIM;
        float acc = 0.f;
        #pragma unroll
        for (int c = 0; c < HDIM / 32; c++)
            acc = fmaf(qs[lane + 32 * c], krow[lane + 32 * c], acc);
        #pragma unroll
        for (int o = 16; o; o >>= 1) acc += __shfl_xor_sync(0xffffffffu, acc, o);
        if (lane == 0) sc[j] = acc;
    }
    __syncthreads();
    float x = -CUDART_INF_F;
    if (tid < 64) {
        x = (tid < nn) ? sc[tid] : -CUDART_INF_F;
        float m = x;
        #pragma unroll
        for (int o = 16; o; o >>= 1) m = fmaxf(m, __shfl_xor_sync(0xffffffffu, m, o));
        if (lane == 0) redbuf[warp] = m;
    }
    __syncthreads();
    const float m = fmaxf(redbuf[0], redbuf[1]);
    float p = 0.f;
    if (tid < 64) {
        p = (tid < nn) ? expf(x - m) : 0.f;
        float ssum = p;
        #pragma unroll
        for (int o = 16; o; o >>= 1) ssum += __shfl_xor_sync(0xffffffffu, ssum, o);
        if (lane == 0) redbuf[4 + warp] = ssum;
    }
    __syncthreads();
    const float inv = 1.f / (redbuf[4] + redbuf[5]);
    if (tid < 64) sc[tid] = p * inv;
    __syncthreads();
    float acc = 0.f;
    for (int j = 0; j < nn; j++)
        acc = fmaf(sc[j], g_v[(size_t)(s + j) * HDIM + tid], acc);
    out[(size_t)i * HDIM + tid] = acc;
}

// ---------------------------------------------------------------------------
extern "C" void kernel_launch(void* const* d_in, const int* in_sizes, int n_in,
                              void* d_out, int out_size)
{
    const float* enc    = (const float*)d_in[0];
    const float* social = (const float*)d_in[1];
    const int*   starts = (const int*)  d_in[2];
    const int*   ends   = (const int*)  d_in[3];
    const float* Wq     = (const float*)d_in[4];
    const float* bq     = (const float*)d_in[5];
    const float* Wk     = (const float*)d_in[6];
    const float* bk     = (const float*)d_in[7];
    const float* Wv     = (const float*)d_in[8];
    const float* bv     = (const float*)d_in[9];
    float* out = (float*)d_out;

    const int B = in_sizes[0] / HDIM;
    const int N = in_sizes[1] / HDIM;

    float* qbuf;
    __nv_bfloat16 *ahi, *alo, *kthi, *ktlo, *vthi, *vtlo;
    cudaGetSymbolAddress((void**)&qbuf, g_q);
    cudaGetSymbolAddress((void**)&ahi,  g_ahi);
    cudaGetSymbolAddress((void**)&alo,  g_alo);
    cudaGetSymbolAddress((void**)&kthi, g_wkt_hi);
    cudaGetSymbolAddress((void**)&ktlo, g_wkt_lo);
    cudaGetSymbolAddress((void**)&vthi, g_wvt_hi);
    cudaGetSymbolAddress((void**)&vtlo, g_wvt_lo);

    cudaFuncSetAttribute(kv_mma_kernel, cudaFuncAttributeMaxDynamicSharedMemorySize, SMEM_BYTES);

    const float inv_sqrt_d = 1.0f / sqrtf((float)HDIM);

    // 1. Split social_ht into bf16 hi/lo
    split_a_kernel<<<(N * HDIM) / (256 * 8), 256>>>(social, ahi, alo);
    // 2. Transpose+split Wk, Wv
    split_w_kernel<<<dim3(HDIM, 2), HDIM>>>(Wk, Wv, kthi, ktlo, vthi, vtlo);
    // 3. Q (scalar, independent)
    gemm_bias_relu<<<dim3(HDIM / 64, B / 64), 256>>>(enc, Wq, bq, qbuf, inv_sqrt_d);
    // 4. K and V via mma.sync bf16 3-split
    kv_mma_kernel<<<dim3(HDIM / 128, N / 128, 2), 256, SMEM_BYTES>>>(bk, bv);
    // 5. Windowed attention
    attn_kernel<<<B, 256>>>(starts, ends, out);
}

// round 5
// speedup vs baseline: 1.9832x; 1.0268x over previous
#include <cuda_runtime.h>
#include <cuda_bf16.h>
#include <math.h>
#include <math_constants.h>
#include <cstdint>

#define HDIM 256
#define MAXB 1024
#define MAXN 32768

// ---------------------------------------------------------------------------
// Scratch (__device__ globals; no dynamic allocation allowed)
// ---------------------------------------------------------------------------
__device__ float g_q[(size_t)MAXB * HDIM];
__device__ float g_k[(size_t)MAXN * HDIM];
__device__ float g_v[(size_t)MAXN * HDIM];
__device__ __nv_bfloat16 g_ahi[(size_t)MAXN * HDIM];   // split of social_ht
__device__ __nv_bfloat16 g_alo[(size_t)MAXN * HDIM];
__device__ __nv_bfloat16 g_wkt_hi[HDIM * HDIM];        // W^T splits: [n][k], k contiguous
__device__ __nv_bfloat16 g_wkt_lo[HDIM * HDIM];
__device__ __nv_bfloat16 g_wvt_hi[HDIM * HDIM];
__device__ __nv_bfloat16 g_wvt_lo[HDIM * HDIM];

// ---------------------------------------------------------------------------
// Prep: split fp32 -> (hi, lo) bf16 pair.  a = hi + lo to ~16 mantissa bits.
// ---------------------------------------------------------------------------
__global__ void __launch_bounds__(256) split_a_kernel(
    const float* __restrict__ src, __nv_bfloat16* __restrict__ hi, __nv_bfloat16* __restrict__ lo)
{
    const size_t base = ((size_t)blockIdx.x * 256 + threadIdx.x) * 8;
    float4 a = *(const float4*)(src + base);
    float4 b = *(const float4*)(src + base + 4);
    __nv_bfloat16 h[8], l[8];
    float v[8] = {a.x, a.y, a.z, a.w, b.x, b.y, b.z, b.w};
    #pragma unroll
    for (int i = 0; i < 8; i++) {
        h[i] = __float2bfloat16(v[i]);
        l[i] = __float2bfloat16(v[i] - __bfloat162float(h[i]));
    }
    *(uint4*)(hi + base) = *(const uint4*)h;
    *(uint4*)(lo + base) = *(const uint4*)l;
}

// Transpose + split both weight matrices: out[n][k] = split(W[k][n])
__global__ void __launch_bounds__(256) split_w_kernel(
    const float* __restrict__ Wk, const float* __restrict__ Wv,
    __nv_bfloat16* __restrict__ khi, __nv_bfloat16* __restrict__ klo,
    __nv_bfloat16* __restrict__ vhi, __nv_bfloat16* __restrict__ vlo)
{
    const int n = blockIdx.x, k = threadIdx.x;
    const float* W = blockIdx.y ? Wv : Wk;
    __nv_bfloat16* oh = blockIdx.y ? vhi : khi;
    __nv_bfloat16* ol = blockIdx.y ? vlo : klo;
    float a = W[k * HDIM + n];
    __nv_bfloat16 h = __float2bfloat16(a);
    oh[n * HDIM + k] = h;
    ol[n * HDIM + k] = __float2bfloat16(a - __bfloat162float(h));
}

// ---------------------------------------------------------------------------
// K/V GEMM via mma.sync.m16n8k16.bf16 with cp.async double-buffered pipeline.
// C[128,128] tile = relu(A @ W^T + bias); 3-MMA split: hi*hi + hi*lo + lo*hi.
// 8 warps = 4(m) x 2(n); warp tile 32x64 = 2 x 8 mma tiles.
// ---------------------------------------------------------------------------
#define KC 64                        // smem K-chunk (bf16 elems)
#define NCHUNK (HDIM / KC)           // 4
#define SROW 72                      // padded smem row stride (elems); 144 B (9*16 -> 16B aligned)
#define TILE_ELEMS (128 * SROW)      // per operand array
#define STAGE_ELEMS (4 * TILE_ELEMS) // Ahi, Alo, Bhi, Blo
#define SMEM_BYTES (2 * STAGE_ELEMS * 2)  // double buffered: 147456

__device__ __forceinline__ uint32_t lds32(const __nv_bfloat16* p, int elem_off) {
    return *(const uint32_t*)(p + elem_off);
}
__device__ __forceinline__ void mma_bf16(float* d, const uint32_t* a, uint32_t b0, uint32_t b1) {
    asm volatile(
        "mma.sync.aligned.m16n8k16.row.col.f32.bf16.bf16.f32 "
        "{%0,%1,%2,%3}, {%4,%5,%6,%7}, {%8,%9}, {%0,%1,%2,%3};\n"
        : "+f"(d[0]), "+f"(d[1]), "+f"(d[2]), "+f"(d[3])
        : "r"(a[0]), "r"(a[1]), "r"(a[2]), "r"(a[3]), "r"(b0), "r"(b1));
}
__device__ __forceinline__ void cp_async16(uint32_t smem_dst, const void* gsrc) {
    asm volatile("cp.async.cg.shared.global [%0], [%1], 16;\n" :: "r"(smem_dst), "l"(gsrc));
}

__global__ void __launch_bounds__(256, 1) kv_mma_kernel(
    const float* __restrict__ bk, const float* __restrict__ bv)
{
    extern __shared__ __nv_bfloat16 sm[];

    const int tid = threadIdx.x;
    const int wid = tid >> 5;
    const int lane = tid & 31;
    const int grp = lane >> 2;      // 0..7
    const int qid = lane & 3;       // 0..3
    const int warp_m = wid & 3;     // 4 warps along m (32 rows each)
    const int warp_n = wid >> 2;    // 2 warps along n (64 cols each)

    const int bn = blockIdx.x;      // n-tile (0..1)
    const int bm = blockIdx.y;      // m-tile (0..255)
    const int mat = blockIdx.z;     // 0 = K, 1 = V

    const __nv_bfloat16* gBhi = mat ? g_wvt_hi : g_wkt_hi;
    const __nv_bfloat16* gBlo = mat ? g_wvt_lo : g_wkt_lo;
    float* C = mat ? g_v : g_k;
    const float* bias = mat ? bv : bk;

    const __nv_bfloat16* gsrc[4] = {g_ahi, g_alo, gBhi, gBlo};
    const int grow[4] = {bm * 128, bm * 128, bn * 128, bn * 128};

    uint32_t smem_u32;
    {
        uint64_t t = __cvta_generic_to_shared(sm);
        smem_u32 = (uint32_t)t;
    }

    // Per-thread load geometry (4 segs of 16B per array): seg = tid + u*256
    // row = seg>>3 (0..127), cs = seg&7 (16B column segment).
    int lrow[4], lcs[4];
    #pragma unroll
    for (int u = 0; u < 4; u++) {
        int seg = u * 256 + tid;
        lrow[u] = seg >> 3;
        lcs[u] = seg & 7;
    }

    auto prefetch = [&](int s, int c) {
        uint32_t stage = smem_u32 + s * (STAGE_ELEMS * 2);
        #pragma unroll
        for (int arr = 0; arr < 4; arr++) {
            const __nv_bfloat16* src = gsrc[arr] + (size_t)grow[arr] * HDIM + c * KC;
            uint32_t dstbase = stage + arr * (TILE_ELEMS * 2);
            #pragma unroll
            for (int u = 0; u < 4; u++) {
                cp_async16(dstbase + lrow[u] * (SROW * 2) + lcs[u] * 16,
                           src + (size_t)lrow[u] * HDIM + lcs[u] * 8);
            }
        }
        asm volatile("cp.async.commit_group;\n");
    };

    float acc[2][8][4] = {};

    prefetch(0, 0);

    for (int c = 0; c < NCHUNK; c++) {
        if (c + 1 < NCHUNK) {
            prefetch((c + 1) & 1, c + 1);
            asm volatile("cp.async.wait_group 1;\n");
        } else {
            asm volatile("cp.async.wait_group 0;\n");
        }
        __syncthreads();

        const __nv_bfloat16* st = sm + (c & 1) * STAGE_ELEMS;
        const __nv_bfloat16* sAhi = st;
        const __nv_bfloat16* sAlo = st + TILE_ELEMS;
        const __nv_bfloat16* sBhi = st + 2 * TILE_ELEMS;
        const __nv_bfloat16* sBlo = st + 3 * TILE_ELEMS;

        #pragma unroll
        for (int ks = 0; ks < KC / 16; ks++) {
            const int k0 = ks * 16;
            uint32_t ahi[2][4], alo[2][4];
            #pragma unroll
            for (int mi = 0; mi < 2; mi++) {
                const int abase = (warp_m * 32 + mi * 16 + grp) * SROW + k0 + 2 * qid;
                ahi[mi][0] = lds32(sAhi, abase);
                ahi[mi][1] = lds32(sAhi, abase + 8 * SROW);
                ahi[mi][2] = lds32(sAhi, abase + 8);
                ahi[mi][3] = lds32(sAhi, abase + 8 * SROW + 8);
                alo[mi][0] = lds32(sAlo, abase);
                alo[mi][1] = lds32(sAlo, abase + 8 * SROW);
                alo[mi][2] = lds32(sAlo, abase + 8);
                alo[mi][3] = lds32(sAlo, abase + 8 * SROW + 8);
            }
            #pragma unroll
            for (int nb = 0; nb < 8; nb++) {
                const int bbase = (warp_n * 64 + nb * 8 + grp) * SROW + k0 + 2 * qid;
                uint32_t bh0 = lds32(sBhi, bbase), bh1 = lds32(sBhi, bbase + 8);
                uint32_t bl0 = lds32(sBlo, bbase), bl1 = lds32(sBlo, bbase + 8);
                #pragma unroll
                for (int mi = 0; mi < 2; mi++) {
                    mma_bf16(acc[mi][nb], ahi[mi], bh0, bh1);
                    mma_bf16(acc[mi][nb], ahi[mi], bl0, bl1);
                    mma_bf16(acc[mi][nb], alo[mi], bh0, bh1);
                }
            }
        }
        __syncthreads();   // readers done before next iteration's prefetch overwrites
    }

    // Epilogue: bias + relu, fp32 stores.
    #pragma unroll
    for (int mi = 0; mi < 2; mi++) {
        const int row = bm * 128 + warp_m * 32 + mi * 16 + grp;
        #pragma unroll
        for (int nb = 0; nb < 8; nb++) {
            const int col = bn * 128 + warp_n * 64 + nb * 8 + 2 * qid;
            float2 bz = *(const float2*)(bias + col);
            float2 o0, o1;
            o0.x = fmaxf(acc[mi][nb][0] + bz.x, 0.f);
            o0.y = fmaxf(acc[mi][nb][1] + bz.y, 0.f);
            o1.x = fmaxf(acc[mi][nb][2] + bz.x, 0.f);
            o1.y = fmaxf(acc[mi][nb][3] + bz.y, 0.f);
            *(float2*)(C + (size_t)row * HDIM + col) = o0;
            *(float2*)(C + (size_t)(row + 8) * HDIM + col) = o1;
        }
    }
}

// ---------------------------------------------------------------------------
// Q GEMM (scalar, tiny: 1024x256x256) — unchanged, known-correct.
// ---------------------------------------------------------------------------
__global__ void __launch_bounds__(256) gemm_bias_relu(
    const float* __restrict__ A, const float* __restrict__ W,
    const float* __restrict__ bias, float* __restrict__ C, float scale)
{
    __shared__ float As[16][65];
    __shared__ float Ws[16][64];
    const int tid = threadIdx.x;
    const int bm = blockIdx.y * 64, bn = blockIdx.x * 64;
    const int tx = tid & 15, ty = tid >> 4;
    const int lm = tid >> 2, lk4 = (tid & 3) * 4;
    const int lwk = tid >> 4, lwn = (tid & 15) * 4;
    const float* Arow = A + (size_t)(bm + lm) * HDIM;
    float acc[4][4] = {};
    for (int k0 = 0; k0 < HDIM; k0 += 16) {
        float4 a4 = *(const float4*)(Arow + k0 + lk4);
        float4 w4 = *(const float4*)(W + (size_t)(k0 + lwk) * HDIM + bn + lwn);
        As[lk4 + 0][lm] = a4.x; As[lk4 + 1][lm] = a4.y;
        As[lk4 + 2][lm] = a4.z; As[lk4 + 3][lm] = a4.w;
        *(float4*)&Ws[lwk][lwn] = w4;
        __syncthreads();
        #pragma unroll
        for (int kk = 0; kk < 16; kk++) {
            float a[4], w[4];
            #pragma unroll
            for (int i = 0; i < 4; i++) a[i] = As[kk][ty * 4 + i];
            #pragma unroll
            for (int j = 0; j < 4; j++) w[j] = Ws[kk][tx * 4 + j];
            #pragma unroll
            for (int i = 0; i < 4; i++)
                #pragma unroll
                for (int j = 0; j < 4; j++)
                    acc[i][j] = fmaf(a[i], w[j], acc[i][j]);
        }
        __syncthreads();
    }
    const int col = bn + tx * 4;
    float c0 = bias[col], c1 = bias[col + 1], c2 = bias[col + 2], c3 = bias[col + 3];
    #pragma unroll
    for (int i = 0; i < 4; i++) {
        const int row = bm + ty * 4 + i;
        float4 r;
        r.x = fmaxf(acc[i][0] + c0, 0.f) * scale;
        r.y = fmaxf(acc[i][1] + c1, 0.f) * scale;
        r.z = fmaxf(acc[i][2] + c2, 0.f) * scale;
        r.w = fmaxf(acc[i][3] + c3, 0.f) * scale;
        *(float4*)(C + (size_t)row * HDIM + col) = r;
    }
}

// ---------------------------------------------------------------------------
// Windowed attention — unchanged, known-correct.
// ---------------------------------------------------------------------------
__global__ void __launch_bounds__(256) attn_kernel(
    const int* __restrict__ starts, const int* __restrict__ ends, float* __restrict__ out)
{
    const int i = blockIdx.x;
    const int tid = threadIdx.x;
    const int warp = tid >> 5, lane = tid & 31;
    __shared__ float qs[HDIM];
    __shared__ float sc[64];
    __shared__ float redbuf[8];
    qs[tid] = g_q[(size_t)i * HDIM + tid];
    const int s = starts[i];
    const int nn = ends[i] - s;
    __syncthreads();
    for (int j = warp; j < nn; j += 8) {
        const float* krow = g_k + (size_t)(s + j) * HDIM;
        float acc = 0.f;
        #pragma unroll
        for (int c = 0; c < HDIM / 32; c++)
            acc = fmaf(qs[lane + 32 * c], krow[lane + 32 * c], acc);
        #pragma unroll
        for (int o = 16; o; o >>= 1) acc += __shfl_xor_sync(0xffffffffu, acc, o);
        if (lane == 0) sc[j] = acc;
    }
    __syncthreads();
    float x = -CUDART_INF_F;
    if (tid < 64) {
        x = (tid < nn) ? sc[tid] : -CUDART_INF_F;
        float m = x;
        #pragma unroll
        for (int o = 16; o; o >>= 1) m = fmaxf(m, __shfl_xor_sync(0xffffffffu, m, o));
        if (lane == 0) redbuf[warp] = m;
    }
    __syncthreads();
    const float m = fmaxf(redbuf[0], redbuf[1]);
    float p = 0.f;
    if (tid < 64) {
        p = (tid < nn) ? expf(x - m) : 0.f;
        float ssum = p;
        #pragma unroll
        for (int o = 16; o; o >>= 1) ssum += __shfl_xor_sync(0xffffffffu, ssum, o);
        if (lane == 0) redbuf[4 + warp] = ssum;
    }
    __syncthreads();
    const float inv = 1.f / (redbuf[4] + redbuf[5]);
    if (tid < 64) sc[tid] = p * inv;
    __syncthreads();
    float acc = 0.f;
    for (int j = 0; j < nn; j++)
        acc = fmaf(sc[j], g_v[(size_t)(s + j) * HDIM + tid], acc);
    out[(size_t)i * HDIM + tid] = acc;
}

// ---------------------------------------------------------------------------
extern "C" void kernel_launch(void* const* d_in, const int* in_sizes, int n_in,
                              void* d_out, int out_size)
{
    const float* enc    = (const float*)d_in[0];
    const float* social = (const float*)d_in[1];
    const int*   starts = (const int*)  d_in[2];
    const int*   ends   = (const int*)  d_in[3];
    const float* Wq     = (const float*)d_in[4];
    const float* bq     = (const float*)d_in[5];
    const float* Wk     = (const float*)d_in[6];
    const float* bk     = (const float*)d_in[7];
    const float* Wv     = (const float*)d_in[8];
    const float* bv     = (const float*)d_in[9];
    float* out = (float*)d_out;

    const int B = in_sizes[0] / HDIM;
    const int N = in_sizes[1] / HDIM;

    float* qbuf;
    __nv_bfloat16 *ahi, *alo, *kthi, *ktlo, *vthi, *vtlo;
    cudaGetSymbolAddress((void**)&qbuf, g_q);
    cudaGetSymbolAddress((void**)&ahi,  g_ahi);
    cudaGetSymbolAddress((void**)&alo,  g_alo);
    cudaGetSymbolAddress((void**)&kthi, g_wkt_hi);
    cudaGetSymbolAddress((void**)&ktlo, g_wkt_lo);
    cudaGetSymbolAddress((void**)&vthi, g_wvt_hi);
    cudaGetSymbolAddress((void**)&vtlo, g_wvt_lo);

    cudaFuncSetAttribute(kv_mma_kernel, cudaFuncAttributeMaxDynamicSharedMemorySize, SMEM_BYTES);

    const float inv_sqrt_d = 1.0f / sqrtf((float)HDIM);

    // 1. Split social_ht into bf16 hi/lo
    split_a_kernel<<<(N * HDIM) / (256 * 8), 256>>>(social, ahi, alo);
    // 2. Transpose+split Wk, Wv
    split_w_kernel<<<dim3(HDIM, 2), HDIM>>>(Wk, Wv, kthi, ktlo, vthi, vtlo);
    // 3. Q (scalar, independent)
    gemm_bias_relu<<<dim3(HDIM / 64, B / 64), 256>>>(enc, Wq, bq, qbuf, inv_sqrt_d);
    // 4. K and V via mma.sync bf16 3-split, cp.async pipelined
    kv_mma_kernel<<<dim3(HDIM / 128, N / 128, 2), 256, SMEM_BYTES>>>(bk, bv);
    // 5. Windowed attention
    attn_kernel<<<B, 256>>>(starts, ends, out);
}